// round 16
// baseline (speedup 1.0000x reference)
#include <cuda_runtime.h>
#include <math.h>

#define N_TOT  8192
#define NF     8
#define HID    64
#define TILE   16
#define NTHR   96               // 2 compute warps + 1 scalar warp
#define NBLK   (N_TOT / TILE)   // 512
#define PIT    20               // H row pitch (floats): 16 samples + 4 pad

typedef unsigned long long ull;

__device__ __forceinline__ float sigm(float x) {
    return 1.0f / (1.0f + __expf(-x));
}

// Accurate tanh (only where it feeds an output directly).
__device__ __forceinline__ float tanh_acc(float x) {
    float ax = fabsf(x);
    if (ax < 0.0625f) {
        float x2 = x * x;
        return x * (1.0f + x2 * (-0.33333333f + x2 * 0.13333334f));
    }
    float e = __expf(-2.0f * ax);
    float r = (1.0f - e) / (1.0f + e);
    return (x < 0.0f) ? -r : r;
}

// HW tanh approximation (MUFU.TANH) for hidden layers.
__device__ __forceinline__ float tanha(float x) {
    float r;
    asm("tanh.approx.f32 %0, %1;" : "=f"(r) : "f"(x));
    return r;
}

// Packed dual-lane FMA (sm_103a FFMA2; ptxas never emits from C++).
__device__ __forceinline__ ull fma2(ull a, ull b, ull c) {
    ull d;
    asm("fma.rn.f32x2 %0, %1, %2, %3;" : "=l"(d) : "l"(a), "l"(b), "l"(c));
    return d;
}
__device__ __forceinline__ float2 unpack2(ull v) {
    float2 r;
    asm("mov.b64 {%0, %1}, %2;" : "=f"(r.x), "=f"(r.y) : "l"(v));
    return r;
}
__device__ __forceinline__ ull dup2(float x) {
    ull d;
    asm("mov.b64 %0, {%1, %1};" : "=l"(d) : "f"(x));
    return d;
}

__device__ __forceinline__ void cp_async16(void* smem_dst, const void* gmem_src) {
    unsigned d = (unsigned)__cvta_generic_to_shared(smem_dst);
    ull g = (ull)__cvta_generic_to_global(gmem_src);
    asm volatile("cp.async.ca.shared.global [%0], [%1], 16;" :: "r"(d), "l"(g));
}

// tanh 8 packed values -> 8 floats of one smem row starting at `row`
__device__ __forceinline__ void tanh_store8(float* row, ull a0, ull a1, ull a2, ull a3) {
    float2 u;
    u = unpack2(a0); *(float2*)&row[0] = make_float2(tanha(u.x), tanha(u.y));
    u = unpack2(a1); *(float2*)&row[2] = make_float2(tanha(u.x), tanha(u.y));
    u = unpack2(a2); *(float2*)&row[4] = make_float2(tanha(u.x), tanha(u.y));
    u = unpack2(a3); *(float2*)&row[6] = make_float2(tanha(u.x), tanha(u.y));
}

__device__ __forceinline__ float warp_sum(float v) {
    v += __shfl_xor_sync(0xFFFFFFFF, v, 16);
    v += __shfl_xor_sync(0xFFFFFFFF, v, 8);
    v += __shfl_xor_sync(0xFFFFFFFF, v, 4);
    v += __shfl_xor_sync(0xFFFFFFFF, v, 2);
    v += __shfl_xor_sync(0xFFFFFFFF, v, 1);
    return v;
}

// ---------------------------------------------------------------------------
// Fused kernel, warp-specialized: 512 blocks x 96 threads.
// Warps 0,1 (compute): each owns 8 samples, 2 cols/lane x 2 MLPs = 16 FFMA2
// chains (the proven R13 hot loop); W2 staged once per block via cp.async.
// Warp 2 (scalar): concurrently loads all scalar params, does the whole
// 128-pt quadrature (4 pts/lane + shfl reduce, no smem round trip) and the
// per-sample MIMICS precomputation (dens*crown, rough*ct^2, ct, st^2), so
// the epilogue after layer 3 is just sigmoid/tanh + Fresnel + 2 logs.
// X staged warp-privately -> no block barrier before layer 1; 3 barriers.
// smem ~45 KB -> ~3.5 resident blocks/SM (was 1.7): serial phases overlap
// across blocks. Quadrature collapse is exact (uniform 32-pt phi-sums of
// cos^k, k<=4, equal the continuous means).
// ---------------------------------------------------------------------------
__global__ __launch_bounds__(NTHR)
void pinn_kernel(const float* __restrict__ X,
                 const float* __restrict__ theta,
                 const float* __restrict__ Wp1, const float* __restrict__ bp1,
                 const float* __restrict__ Wp2, const float* __restrict__ bp2,
                 const float* __restrict__ Wp3, const float* __restrict__ bp3,
                 const float* __restrict__ Wc1, const float* __restrict__ bc1,
                 const float* __restrict__ Wc2, const float* __restrict__ bc2,
                 const float* __restrict__ Wc3, const float* __restrict__ bc3,
                 const float* __restrict__ nb_raw, const float* __restrict__ nl_raw,
                 const float* __restrict__ so_raw, const float* __restrict__ mg_raw,
                 const float* __restrict__ s_raw,
                 float* __restrict__ out) {
    __shared__ __align__(16) float Wp2s[HID][HID];   // 16 KB staged weights
    __shared__ __align__(16) float Wc2s[HID][HID];   // 16 KB
    __shared__ __align__(16) float XT[NF][PIT];      // [feature][sample]
    __shared__ __align__(16) float Hp[HID][PIT];     // H1, reused as H2
    __shared__ __align__(16) float Hc[HID][PIT];
    __shared__ float Ys[2][TILE];
    __shared__ float pcv[TILE], pch[TILE];           // dens*crown_{vv,vh}
    __shared__ float g0s[TILE];                      // rough*ct^2
    __shared__ float cts[TILE], st2s[TILE];

    const int t    = threadIdx.x;       // 0..95
    const int lane = t & 31;
    const int w    = t >> 5;            // 0,1 compute; 2 scalar
    const int base = blockIdx.x * TILE;
    const float PI = 3.14159265358979f;

    // ---- all warps: issue W2 staging cp.asyncs FIRST ----
    {
        const float4* gp = (const float4*)Wp2;   // 1024 float4 each
        const float4* gc = (const float4*)Wc2;
        float4* sp = (float4*)&Wp2s[0][0];
        float4* sc = (float4*)&Wc2s[0][0];
        for (int j = t; j < 1024; j += NTHR) cp_async16(&sp[j], &gp[j]);
        for (int j = t; j < 1024; j += NTHR) cp_async16(&sc[j], &gc[j]);
        asm volatile("cp.async.commit_group;" ::: "memory");
    }

    if (w < 2) {
        // ================= COMPUTE WARPS =================
        const int sgo = w * 8;         // first sample owned
        const int c2  = 2 * lane;      // columns owned

        // warp-private X staging: 64 consecutive floats = 32 float2
        {
            float2 v = ((const float2*)(X + (base + sgo) * NF))[lane];
            int idx = 2 * lane;
            int r = idx >> 3, k = idx & 7;   // k even, k+1 = odd partner
            XT[k][sgo + r]     = v.x;
            XT[k + 1][sgo + r] = v.y;
        }
        __syncwarp();

        ull ap00, ap01, ap02, ap03, ap10, ap11, ap12, ap13;
        ull ac00, ac01, ac02, ac03, ac10, ac11, ac12, ac13;

        // ---- layer 1 (both MLPs): K = 8 ----
        {
            float2 bp = __ldg((const float2*)(bp1 + c2));
            float2 bc = __ldg((const float2*)(bc1 + c2));
            ull b;
            b = dup2(bp.x); ap00 = b; ap01 = b; ap02 = b; ap03 = b;
            b = dup2(bp.y); ap10 = b; ap11 = b; ap12 = b; ap13 = b;
            b = dup2(bc.x); ac00 = b; ac01 = b; ac02 = b; ac03 = b;
            b = dup2(bc.y); ac10 = b; ac11 = b; ac12 = b; ac13 = b;
            #pragma unroll
            for (int k = 0; k < NF; k++) {
                ulonglong2 A0 = *(const ulonglong2*)&XT[k][sgo];
                ulonglong2 A1 = *(const ulonglong2*)&XT[k][sgo + 4];
                float2 wpv = __ldg((const float2*)(Wp1 + k * HID + c2));
                float2 wcv = __ldg((const float2*)(Wc1 + k * HID + c2));
                ull wp0 = dup2(wpv.x), wp1 = dup2(wpv.y);
                ull wc0 = dup2(wcv.x), wc1 = dup2(wcv.y);
                ap00 = fma2(A0.x, wp0, ap00); ap01 = fma2(A0.y, wp0, ap01);
                ap02 = fma2(A1.x, wp0, ap02); ap03 = fma2(A1.y, wp0, ap03);
                ap10 = fma2(A0.x, wp1, ap10); ap11 = fma2(A0.y, wp1, ap11);
                ap12 = fma2(A1.x, wp1, ap12); ap13 = fma2(A1.y, wp1, ap13);
                ac00 = fma2(A0.x, wc0, ac00); ac01 = fma2(A0.y, wc0, ac01);
                ac02 = fma2(A1.x, wc0, ac02); ac03 = fma2(A1.y, wc0, ac03);
                ac10 = fma2(A0.x, wc1, ac10); ac11 = fma2(A0.y, wc1, ac11);
                ac12 = fma2(A1.x, wc1, ac12); ac13 = fma2(A1.y, wc1, ac13);
            }
            tanh_store8(&Hp[c2    ][sgo], ap00, ap01, ap02, ap03);
            tanh_store8(&Hp[c2 + 1][sgo], ap10, ap11, ap12, ap13);
            tanh_store8(&Hc[c2    ][sgo], ac00, ac01, ac02, ac03);
            tanh_store8(&Hc[c2 + 1][sgo], ac10, ac11, ac12, ac13);
        }
        asm volatile("cp.async.wait_group 0;" ::: "memory");
        __syncthreads();   // sync1: W2s visible (H is warp-private)

        // ---- layer 2 (both MLPs): K = 64, weights from SMEM ----
        {
            float2 bp = __ldg((const float2*)(bp2 + c2));
            float2 bc = __ldg((const float2*)(bc2 + c2));
            ull b;
            b = dup2(bp.x); ap00 = b; ap01 = b; ap02 = b; ap03 = b;
            b = dup2(bp.y); ap10 = b; ap11 = b; ap12 = b; ap13 = b;
            b = dup2(bc.x); ac00 = b; ac01 = b; ac02 = b; ac03 = b;
            b = dup2(bc.y); ac10 = b; ac11 = b; ac12 = b; ac13 = b;

            float2 nWp = *(const float2*)&Wp2s[0][c2];
            float2 nWc = *(const float2*)&Wc2s[0][c2];
            ulonglong2 nAp0 = *(const ulonglong2*)&Hp[0][sgo];
            ulonglong2 nAp1 = *(const ulonglong2*)&Hp[0][sgo + 4];
            ulonglong2 nAc0 = *(const ulonglong2*)&Hc[0][sgo];
            ulonglong2 nAc1 = *(const ulonglong2*)&Hc[0][sgo + 4];

            #pragma unroll 8
            for (int k = 0; k < HID; k++) {
                ull wp0 = dup2(nWp.x), wp1 = dup2(nWp.y);
                ull wc0 = dup2(nWc.x), wc1 = dup2(nWc.y);
                ulonglong2 Ap0 = nAp0, Ap1 = nAp1, Ac0 = nAc0, Ac1 = nAc1;
                if (k + 1 < HID) {
                    nWp  = *(const float2*)&Wp2s[k + 1][c2];
                    nWc  = *(const float2*)&Wc2s[k + 1][c2];
                    nAp0 = *(const ulonglong2*)&Hp[k + 1][sgo];
                    nAp1 = *(const ulonglong2*)&Hp[k + 1][sgo + 4];
                    nAc0 = *(const ulonglong2*)&Hc[k + 1][sgo];
                    nAc1 = *(const ulonglong2*)&Hc[k + 1][sgo + 4];
                }
                ap00 = fma2(Ap0.x, wp0, ap00); ap01 = fma2(Ap0.y, wp0, ap01);
                ap02 = fma2(Ap1.x, wp0, ap02); ap03 = fma2(Ap1.y, wp0, ap03);
                ap10 = fma2(Ap0.x, wp1, ap10); ap11 = fma2(Ap0.y, wp1, ap11);
                ap12 = fma2(Ap1.x, wp1, ap12); ap13 = fma2(Ap1.y, wp1, ap13);
                ac00 = fma2(Ac0.x, wc0, ac00); ac01 = fma2(Ac0.y, wc0, ac01);
                ac02 = fma2(Ac1.x, wc0, ac02); ac03 = fma2(Ac1.y, wc0, ac03);
                ac10 = fma2(Ac0.x, wc1, ac10); ac11 = fma2(Ac0.y, wc1, ac11);
                ac12 = fma2(Ac1.x, wc1, ac12); ac13 = fma2(Ac1.y, wc1, ac13);
            }
        }
        __syncwarp();   // this warp done reading its H1 samples
        tanh_store8(&Hp[c2    ][sgo], ap00, ap01, ap02, ap03);
        tanh_store8(&Hp[c2 + 1][sgo], ap10, ap11, ap12, ap13);
        tanh_store8(&Hc[c2    ][sgo], ac00, ac01, ac02, ac03);
        tanh_store8(&Hc[c2 + 1][sgo], ac10, ac11, ac12, ac13);
        __syncthreads();   // sync2: H2 (all 16 samples) visible

        // ---- layer 3: warp w handles MLP w, 16 dots, 2 lanes/dot ----
        {
            int d    = lane >> 1;           // sample 0..15
            int half = lane & 1;
            const float* W3 = w ? Wc3 : Wp3;
            const float* H2 = w ? &Hc[0][0] : &Hp[0][0];
            float v0 = half ? 0.f : __ldg(w ? bc3 : bp3);
            float v1 = 0.f;
            #pragma unroll 8
            for (int j = 0; j < 32; j += 2) {
                int k0 = 2 * j + half;
                int k1 = 2 * (j + 1) + half;
                v0 = fmaf(H2[k0 * PIT + d], __ldg(W3 + k0), v0);
                v1 = fmaf(H2[k1 * PIT + d], __ldg(W3 + k1), v1);
            }
            float v = v0 + v1;
            v += __shfl_xor_sync(0xFFFFFFFF, v, 1);
            if (half == 0) Ys[w][d] = v;
        }
        __syncthreads();   // sync3: Ys + scalar-warp precomp visible
    } else {
        // ================= SCALAR WARP =================
        // scalar params (uniform loads)
        float sig_o = (10.0f + 70.0f * sigm(so_raw[0])) * (PI / 180.0f);
        float inv2s2 = 1.0f / (2.0f * sig_o * sig_o);

        // 128-pt quadrature: 4 points per lane, local accumulate
        float m0 = 0.f, m1 = 0.f, m2 = 0.f, m3 = 0.f;
        #pragma unroll
        for (int ii = 0; ii < 4; ii++) {
            int i = lane + 32 * ii;
            float th = (float)i * (PI * 0.5f / 127.0f);
            float d  = th - PI * 0.25f;
            float sn, cn;
            __sincosf(th, &sn, &cn);
            float pdf = __expf(-d * d * inv2s2) * sn;
            float c2v = cn * cn, s2v = sn * sn;
            m0 += pdf;
            m1 += pdf * c2v * c2v;
            m2 += pdf * c2v * s2v;
            m3 += pdf * s2v * s2v;
        }
        m0 = warp_sum(m0); m1 = warp_sum(m1);
        m2 = warp_sum(m2); m3 = warp_sum(m3);
        float inv = 1.0f / m0;
        float S1 = m1 * inv, S2 = m2 * inv, S3 = m3 * inv;

        const float LN10 = 2.302585093f;
        float Nb = __expf((2.0f + 3.0f * sigm(nb_raw[0])) * LN10);
        float Nl = __expf((3.0f + 3.0f * sigm(nl_raw[0])) * LN10);
        float dens = Nb * 1e-4f + Nl * 1e-6f;

        float mg   = 0.05f + 0.75f * sigm(mg_raw[0]);
        float epsv = 1.5f + 20.0f * mg;
        float Kv   = (epsv - 1.0f) / (epsv + 2.0f);
        float Kv2  = Kv * Kv;

        float sm = 0.01f * (0.5f + 5.5f * sigm(s_raw[0]));
        float kw = 2.0f * PI * (5.405e9f / 2.998e8f);
        float tt = 2.0f * kw * sm;
        float c_r = tt * tt;

        // per-sample precomputation (lanes 0..15)
        if (lane < TILE) {
            float ti = theta[base + lane] * (PI / 180.0f);
            float ct, st;
            __sincosf(ti, &st, &ct);
            float ct2 = ct * ct, st2 = st * st;
            float cvv = Kv2 * (ct2 * ct2 * S1 + 3.0f * ct2 * st2 * S2
                               + 0.375f * st2 * st2 * S3);
            float cvh = Kv2 * (0.5f * ct2 * S2 + 0.125f * st2 * S3);
            pcv[lane]  = dens * cvv;
            pch[lane]  = dens * cvh;
            g0s[lane]  = __expf(-c_r * ct2) * ct2;   // rough * ct^2
            cts[lane]  = ct;
            st2s[lane] = st2;
        }
        asm volatile("cp.async.wait_group 0;" ::: "memory");
        __syncthreads();   // sync1
        __syncthreads();   // sync2
        __syncthreads();   // sync3
    }

    // ---- epilogue (warp 0 lanes 0..15): short, everything precomputed ----
    if (t < TILE) {
        int s = base + t;

        float m_v   = 0.93f * sigm(Ys[0][t]);
        float delta = 0.05f * tanh_acc(Ys[1][t]);   // direct output: exact tanh
        float eps_g = 3.0f + 25.0f * m_v + 10.0f * m_v * m_v;

        float ct  = cts[t];
        float st2 = st2s[t];
        float root  = sqrtf(eps_g - st2);
        float ec    = eps_g * ct;
        float r_v   = (ec - root) / (ec + root);
        float gamma = r_v * r_v;
        float ground = gamma * g0s[t];

        float svv = pcv[t] + ground;
        float svh = pch[t] + 0.05f * ground;

        const float ILN10_10 = 4.342944819f;   // 10 / ln(10)
        out[0 * N_TOT + s] = m_v;
        out[1 * N_TOT + s] = delta;
        out[2 * N_TOT + s] = m_v + delta;
        out[3 * N_TOT + s] = __logf(svv + 1e-12f) * ILN10_10;
        out[4 * N_TOT + s] = __logf(svh + 1e-12f) * ILN10_10;
        out[5 * N_TOT + s] = eps_g;
    }
}

extern "C" void kernel_launch(void* const* d_in, const int* in_sizes, int n_in,
                              void* d_out, int out_size) {
    // inputs: 0 X, 1 theta_inc_deg, 2 vv_db_observed (unused),
    // 3 Wp1, 4 bp1, 5 Wp2, 6 bp2, 7 Wp3, 8 bp3,
    // 9 Wc1, 10 bc1, 11 Wc2, 12 bc2, 13 Wc3, 14 bc3,
    // 15 nb_raw, 16 nl_raw, 17 so_raw, 18 mg_raw, 19 s_raw
    (void)in_sizes; (void)n_in; (void)out_size;

    pinn_kernel<<<NBLK, NTHR>>>(
        (const float*)d_in[0], (const float*)d_in[1],
        (const float*)d_in[3], (const float*)d_in[4],
        (const float*)d_in[5], (const float*)d_in[6],
        (const float*)d_in[7], (const float*)d_in[8],
        (const float*)d_in[9], (const float*)d_in[10],
        (const float*)d_in[11], (const float*)d_in[12],
        (const float*)d_in[13], (const float*)d_in[14],
        (const float*)d_in[15], (const float*)d_in[16],
        (const float*)d_in[17], (const float*)d_in[18],
        (const float*)d_in[19],
        (float*)d_out);
}